// round 7
// baseline (speedup 1.0000x reference)
#include <cuda_runtime.h>

// Problem constants: B=8, CIN=COUT=128, H=W=64
#define NB   8
#define NC   128
#define NH   64
#define NW   64

// Scratch (device globals — no allocation allowed)
__device__ __align__(16) float g_xt[NB * NH * NW * NC];   // NHWC input, 16 MB
__device__ __align__(16) float g_off[NB * NH * NW * 4];   // shift_y, shift_x, scale1, scale2
__device__ __align__(16) float g_wt2[9 * 64 * 256];       // [k][cp][o][j]: w[o][2cp+j][k]

__constant__ float c_BY[9] = {-1,-1,-1, 0,0,0, 1,1,1};
__constant__ float c_BX[9] = {-1, 0, 1,-1,0,1,-1,0,1};

// dynamic smem (shared across kernels)
extern __shared__ float dsm[];

// k_main dynamic smem layout (floats)
#define SOFF0 0         // sample buf 0: [64 px][128 c]
#define SOFF1 8192      // sample buf 1
#define WOFF0 16384     // weight chunk buf 0: [32 cp][16 og][20] (16 used + 4 pad)
#define WOFF1 26624     // weight chunk buf 1
#define KMAIN_SMEM (36864 * 4)

// ---------------------------------------------------------------------------
// PTX helpers
// ---------------------------------------------------------------------------
__device__ __forceinline__ unsigned smaddr(const void* p) {
    return (unsigned)__cvta_generic_to_shared(p);
}
__device__ __forceinline__ void mb_init(unsigned a, unsigned cnt) {
    asm volatile("mbarrier.init.shared.b64 [%0], %1;" :: "r"(a), "r"(cnt) : "memory");
}
__device__ __forceinline__ void mb_arrive(unsigned a) {
    asm volatile("mbarrier.arrive.shared.b64 _, [%0];" :: "r"(a) : "memory");
}
__device__ __forceinline__ void mb_wait(unsigned a, unsigned ph) {
    asm volatile(
        "{\n\t"
        ".reg .pred P;\n\t"
        "WL%=:\n\t"
        "mbarrier.try_wait.parity.acquire.cta.shared::cta.b64 P, [%0], %1, 0x989680;\n\t"
        "@!P bra WL%=;\n\t"
        "}" :: "r"(a), "r"(ph) : "memory");
}
__device__ __forceinline__ void cpa16(unsigned d, const float* s) {
    asm volatile("cp.async.cg.shared.global [%0], [%1], 16;" :: "r"(d), "l"(s) : "memory");
}
__device__ __forceinline__ void cpa_commit() {
    asm volatile("cp.async.commit_group;" ::: "memory");
}
__device__ __forceinline__ void cpa_wait1() {
    asm volatile("cp.async.wait_group 1;" ::: "memory");
}
__device__ __forceinline__ void cpa_wait0() {
    asm volatile("cp.async.wait_group 0;" ::: "memory");
}
__device__ __forceinline__ void barC() {   // consumer-only named barrier (8 warps)
    asm volatile("bar.sync 1, 256;" ::: "memory");
}

// ---------------------------------------------------------------------------
// Kernel 1: NCHW -> NHWC transpose
// ---------------------------------------------------------------------------
__global__ void k_transpose(const float* __restrict__ x) {
    __shared__ float tile[32][33];
    int bh = blockIdx.x;
    int b = bh >> 6, h = bh & 63;
    int c0 = blockIdx.y * 32;
    int w0 = blockIdx.z * 32;
    int tx = threadIdx.x, ty = threadIdx.y;
#pragma unroll
    for (int q = 0; q < 4; q++) {
        int c = c0 + ty + 8 * q;
        tile[ty + 8 * q][tx] = x[(((b * NC + c) * NH + h) * NW) + w0 + tx];
    }
    __syncthreads();
#pragma unroll
    for (int q = 0; q < 4; q++) {
        int w = w0 + ty + 8 * q;
        g_xt[((b * NH + h) * NW + w) * NC + c0 + tx] = tile[tx][ty + 8 * q];
    }
}

// ---------------------------------------------------------------------------
// Kernel 2: w[o][c][k] -> g_wt2[k][cp][o][j] = w[o][2cp+j][k]  (channel pairs)
// ---------------------------------------------------------------------------
__global__ void k_wt2(const float* __restrict__ w) {
    int i = blockIdx.x * 256 + threadIdx.x;
    if (i < 9 * 64 * 256) {
        int k = i / 16384;
        int r = i & 16383;
        int cp = r >> 8;
        int o = (r >> 1) & 127;
        int j = r & 1;
        g_wt2[i] = w[(o * NC + 2 * cp + j) * 9 + k];
    }
}

// ---------------------------------------------------------------------------
// Kernel 3: offset conv -> g_off
// ---------------------------------------------------------------------------
__global__ void __launch_bounds__(256) k_off(const float* __restrict__ w_off,
                                             const float* __restrict__ b_off) {
    float* xin = dsm;                  // [3][64][128]
    float* sw  = dsm + 3 * NW * NC;    // [4][9][128]
    int h = blockIdx.x, b = blockIdx.y;
    int t = threadIdx.x;

    for (int r = 0; r < 3; r++) {
        int hr = h + r - 1;
        float4* dst = (float4*)(xin + r * NW * NC);
        if (hr >= 0 && hr < NH) {
            const float4* src = (const float4*)(g_xt + ((b * NH + hr) * NW) * NC);
            for (int i = t; i < (NW * NC) / 4; i += 256) dst[i] = src[i];
        } else {
            for (int i = t; i < (NW * NC) / 4; i += 256) dst[i] = make_float4(0.f, 0.f, 0.f, 0.f);
        }
    }
    for (int i = t; i < 4 * 9 * NC; i += 256) {
        int j = i / (9 * NC);
        int r2 = i % (9 * NC);
        int tap = r2 >> 7, c = r2 & 127;
        sw[i] = w_off[(j * NC + c) * 9 + tap];
    }
    __syncthreads();

    int wid = t >> 5, lane = t & 31;
    for (int it = 0; it < 8; it++) {
        int p = it * 8 + wid;
        float a0 = 0.f, a1 = 0.f, a2 = 0.f, a3 = 0.f;
#pragma unroll
        for (int tap = 0; tap < 9; tap++) {
            int dx = tap % 3 - 1;
            int dy = tap / 3;
            int xx = p + dx;
            if (xx < 0 || xx >= NW) continue;
            float4 xv = *(const float4*)(xin + (dy * NW + xx) * NC + lane * 4);
            float4 w0 = *(const float4*)(sw + (0 * 9 + tap) * NC + lane * 4);
            float4 w1 = *(const float4*)(sw + (1 * 9 + tap) * NC + lane * 4);
            float4 w2 = *(const float4*)(sw + (2 * 9 + tap) * NC + lane * 4);
            float4 w3 = *(const float4*)(sw + (3 * 9 + tap) * NC + lane * 4);
            a0 += xv.x * w0.x + xv.y * w0.y + xv.z * w0.z + xv.w * w0.w;
            a1 += xv.x * w1.x + xv.y * w1.y + xv.z * w1.z + xv.w * w1.w;
            a2 += xv.x * w2.x + xv.y * w2.y + xv.z * w2.z + xv.w * w2.w;
            a3 += xv.x * w3.x + xv.y * w3.y + xv.z * w3.z + xv.w * w3.w;
        }
#pragma unroll
        for (int off = 16; off; off >>= 1) {
            a0 += __shfl_xor_sync(0xffffffffu, a0, off);
            a1 += __shfl_xor_sync(0xffffffffu, a1, off);
            a2 += __shfl_xor_sync(0xffffffffu, a2, off);
            a3 += __shfl_xor_sync(0xffffffffu, a3, off);
        }
        if (lane == 0) {
            float sy = a0 + b_off[0];
            float sx = a1 + b_off[1];
            float s1 = fmaxf(a2 + b_off[2], 0.f) + 1.f;
            float s2 = fmaxf(a3 + b_off[3], 0.f) + 1.f;
            *(float4*)(g_off + ((b * NH + h) * NW + p) * 4) = make_float4(sy, sx, s1, s2);
        }
    }
}

// ---------------------------------------------------------------------------
// Kernel 4: warp-specialized deformable conv, smem-staged weights.
// grid (NH, NB): block = one (b,h) row, 64 pixels x 128 outputs.
// 288 threads: warps 0-7 = consumers (GEMM + weight cp.async), warp 8 = sampler.
// Weights: 18 chunks of 32KB (half-tap), double-buffered, cp.async prefetch
//          distance 1, two named consumer barriers per chunk.
// Samples: [64][128] double-buffered by tap parity, mbarrier pipeline.
// GEMM: thread = 4 px x 8 outs, channel-paired f32x2 accumulators.
// ---------------------------------------------------------------------------
__device__ __forceinline__ void corner_math(int h, int pw, int k, float4 pr,
                                            float4* cw_s, int4* ci_s) {
    float sc = (k & 1) ? pr.w : pr.z;
    float py = (float)h + c_BY[k] * sc + pr.x;
    float px = (float)pw + c_BX[k] * sc + pr.y;
    float y0f = floorf(py), x0f = floorf(px);
    float wy = py - y0f, wx = px - x0f;
    int y0 = (int)y0f, x0 = (int)x0f;
    int y1 = y0 + 1, x1 = x0 + 1;
    float w00 = (1.f - wy) * (1.f - wx);
    float w01 = (1.f - wy) * wx;
    float w10 = wy * (1.f - wx);
    float w11 = wy * wx;
    bool vy0 = (y0 >= 0) && (y0 < NH), vy1 = (y1 >= 0) && (y1 < NH);
    bool vx0 = (x0 >= 0) && (x0 < NW), vx1 = (x1 >= 0) && (x1 < NW);
    int cy0 = min(max(y0, 0), NH - 1), cy1 = min(max(y1, 0), NH - 1);
    int cx0 = min(max(x0, 0), NW - 1), cx1 = min(max(x1, 0), NW - 1);
    *cw_s = make_float4((vy0 && vx0) ? w00 : 0.f,
                        (vy0 && vx1) ? w01 : 0.f,
                        (vy1 && vx0) ? w10 : 0.f,
                        (vy1 && vx1) ? w11 : 0.f);
    *ci_s = make_int4((cy0 * NW + cx0) * NC, (cy0 * NW + cx1) * NC,
                      (cy1 * NW + cx0) * NC, (cy1 * NW + cx1) * NC);
}

__global__ void __launch_bounds__(288, 1) k_main(const float* __restrict__ bias,
                                                 float* __restrict__ out) {
    __shared__ __align__(16) int4   ci_s[64];
    __shared__ __align__(16) float4 cw_s[64];
    __shared__ __align__(8)  unsigned long long mbar[4]; // full0, full1, empty0, empty1

    int h = blockIdx.x;
    int b = blockIdx.y;
    int t = threadIdx.x;

    unsigned mb_base = smaddr(&mbar[0]);
    if (t == 0) {
        mb_init(mb_base + 0,  32);  // full0 (all sampler lanes arrive)
        mb_init(mb_base + 8,  32);  // full1
        mb_init(mb_base + 16, 8);   // empty0 (one per consumer warp)
        mb_init(mb_base + 24, 8);   // empty1
    }
    __syncthreads();

    const float* xb = g_xt + (size_t)b * (NH * NW * NC);

    if (t >= 256) {
        // ================= SAMPLER (warp 8) =================
        int lane = t - 256;
        float4 prA = *(const float4*)(g_off + ((b * NH + h) * NW + lane) * 4);
        float4 prB = *(const float4*)(g_off + ((b * NH + h) * NW + lane + 32) * 4);

        for (int k = 0; k < 9; k++) {
            int buf = k & 1;
            if (k >= 2) mb_wait(mb_base + 16 + 8 * buf, ((k >> 1) - 1) & 1);

            corner_math(h, lane,      k, prA, &cw_s[lane],      &ci_s[lane]);
            corner_math(h, lane + 32, k, prB, &cw_s[lane + 32], &ci_s[lane + 32]);
            __syncwarp();

            float* sb = dsm + buf * 8192;
#pragma unroll 4
            for (int p = 0; p < 64; p++) {
                int4 ci = ci_s[p];
                float4 cw = cw_s[p];
                float4 v00 = *(const float4*)(xb + ci.x + lane * 4);
                float4 v01 = *(const float4*)(xb + ci.y + lane * 4);
                float4 v10 = *(const float4*)(xb + ci.z + lane * 4);
                float4 v11 = *(const float4*)(xb + ci.w + lane * 4);
                float4 s;
                s.x = cw.x * v00.x + cw.y * v01.x + cw.z * v10.x + cw.w * v11.x;
                s.y = cw.x * v00.y + cw.y * v01.y + cw.z * v10.y + cw.w * v11.y;
                s.z = cw.x * v00.z + cw.y * v01.z + cw.z * v10.z + cw.w * v11.z;
                s.w = cw.x * v00.w + cw.y * v01.w + cw.z * v10.w + cw.w * v11.w;
                *(float4*)(sb + p * 128 + lane * 4) = s;
            }
            __syncwarp();
            mb_arrive(mb_base + 8 * buf);    // all 32 lanes arrive (release own STS)
        }
    } else {
        // ================= CONSUMERS (warps 0-7) =================
        int tm = t >> 4;      // pixel group: m = 4*tm .. 4*tm+3   (half-warp uniform)
        int to = t & 15;      // output group: o = 8*to .. 8*to+7

        unsigned long long acc[32];
#pragma unroll
        for (int i = 0; i < 32; i++) acc[i] = 0ull;

        // weight chunk copy: thread t covers rows r = 2t, 2t+1 of [32cp][16og]
        auto issue_chunk = [&](int cc) {
            int k = cc >> 1, hf = cc & 1;
            unsigned wdst = smaddr(dsm + ((cc & 1) ? WOFF1 : WOFF0));
            const float* wsrc = g_wt2 + k * 16384 + hf * 8192;
#pragma unroll
            for (int rr = 0; rr < 2; rr++) {
                int r = 2 * t + rr;
                int cp = r >> 4, og = r & 15;
                const float* s = wsrc + cp * 256 + og * 16;
                unsigned d = wdst + (cp * 320 + og * 20) * 4;
#pragma unroll
                for (int sgm = 0; sgm < 4; sgm++)
                    cpa16(d + sgm * 16, s + sgm * 4);
            }
        };

        issue_chunk(0);
        cpa_commit();

        for (int cc = 0; cc < 18; cc++) {
            int k = cc >> 1, hf = cc & 1;

            barC();                                   // safe to overwrite wbuf[(cc+1)&1]
            if (cc < 17) { issue_chunk(cc + 1); cpa_commit(); cpa_wait1(); }
            else         { cpa_wait0(); }
            if (hf == 0) mb_wait(mb_base + 8 * (k & 1), (k >> 1) & 1);   // samples ready
            barC();                                   // weight chunk visible

            const float* sb = dsm + (k & 1) * 8192 + tm * 512 + hf * 64;
            const float* wb = dsm + ((cc & 1) ? WOFF1 : WOFF0) + to * 20;
#pragma unroll 4
            for (int q = 0; q < 16; q++) {
                unsigned long long sA[4], sB[4];
#pragma unroll
                for (int i = 0; i < 4; i++) {
                    ulonglong2 sv = *(const ulonglong2*)(sb + i * 128 + q * 4);
                    sA[i] = sv.x;
                    sB[i] = sv.y;
                }
                const float* we = wb + (2 * q) * 320;
                ulonglong2 e0 = ((const ulonglong2*)we)[0];
                ulonglong2 e1 = ((const ulonglong2*)we)[1];
                ulonglong2 e2 = ((const ulonglong2*)we)[2];
                ulonglong2 e3 = ((const ulonglong2*)we)[3];
                const float* wo = we + 320;
                ulonglong2 o0 = ((const ulonglong2*)wo)[0];
                ulonglong2 o1 = ((const ulonglong2*)wo)[1];
                ulonglong2 o2 = ((const ulonglong2*)wo)[2];
                ulonglong2 o3 = ((const ulonglong2*)wo)[3];
                unsigned long long wE[8] = {e0.x, e0.y, e1.x, e1.y, e2.x, e2.y, e3.x, e3.y};
                unsigned long long wO[8] = {o0.x, o0.y, o1.x, o1.y, o2.x, o2.y, o3.x, o3.y};
#pragma unroll
                for (int i = 0; i < 4; i++)
#pragma unroll
                    for (int oi = 0; oi < 8; oi++) {
                        asm("fma.rn.f32x2 %0, %1, %2, %0;"
                            : "+l"(acc[i * 8 + oi]) : "l"(wE[oi]), "l"(sA[i]));
                        asm("fma.rn.f32x2 %0, %1, %2, %0;"
                            : "+l"(acc[i * 8 + oi]) : "l"(wO[oi]), "l"(sB[i]));
                    }
            }
            if (hf == 1 && (t & 31) == 0) mb_arrive(mb_base + 16 + 8 * (k & 1));
        }

        // ---- epilogue: direct STG.128, 4 px per output ----
        int to8 = to * 8;
        float4 bs0 = *(const float4*)(bias + to8);
        float4 bs1 = *(const float4*)(bias + to8 + 4);
        float bsv[8] = {bs0.x, bs0.y, bs0.z, bs0.w, bs1.x, bs1.y, bs1.z, bs1.w};
#pragma unroll
        for (int oi = 0; oi < 8; oi++) {
            float v[4];
#pragma unroll
            for (int i = 0; i < 4; i++) {
                float lo, hi;
                asm("mov.b64 {%0, %1}, %2;" : "=f"(lo), "=f"(hi) : "l"(acc[i * 8 + oi]));
                v[i] = lo + hi + bsv[oi];
            }
            float* op = out + (((size_t)b * NC + to8 + oi) * NH + h) * NW + tm * 4;
            *(float4*)op = make_float4(v[0], v[1], v[2], v[3]);
        }
    }
}

// ---------------------------------------------------------------------------
extern "C" void kernel_launch(void* const* d_in, const int* in_sizes, int n_in,
                              void* d_out, int out_size) {
    const float* x     = (const float*)d_in[0];
    const float* w_off = (const float*)d_in[1];
    const float* b_off = (const float*)d_in[2];
    const float* w     = (const float*)d_in[3];
    const float* bias  = (const float*)d_in[4];
    float* out = (float*)d_out;

    k_transpose<<<dim3(NB * NH, NC / 32, NW / 32), dim3(32, 8)>>>(x);
    k_wt2<<<(9 * 64 * 256 + 255) / 256, 256>>>(w);

    int off_smem = (3 * NW * NC + 4 * 9 * NC) * (int)sizeof(float);   // 116 KB
    cudaFuncSetAttribute(k_off, cudaFuncAttributeMaxDynamicSharedMemorySize, off_smem);
    k_off<<<dim3(NH, NB), 256, off_smem>>>(w_off, b_off);

    cudaFuncSetAttribute(k_main, cudaFuncAttributeMaxDynamicSharedMemorySize, KMAIN_SMEM);
    k_main<<<dim3(NH, NB), 288, KMAIN_SMEM>>>(bias, out);
}

// round 10
// speedup vs baseline: 1.6551x; 1.6551x over previous
#include <cuda_runtime.h>

// Problem constants: B=8, CIN=COUT=128, H=W=64
#define NB   8
#define NC   128
#define NH   64
#define NW   64

// Scratch (device globals — no allocation allowed)
__device__ __align__(16) float g_xt[NB * NH * NW * NC];   // NHWC input, 16 MB
__device__ __align__(16) float g_off[NB * NH * NW * 4];   // shift_y, shift_x, scale1, scale2
__device__ __align__(16) float g_wt3[9 * 16384];          // [k][og16][cp64][m4][4]

__constant__ float c_BY[9] = {-1,-1,-1, 0,0,0, 1,1,1};
__constant__ float c_BX[9] = {-1, 0, 1,-1,0,1,-1,0,1};

extern __shared__ float dsm[];

// k_main smem layout (floats): s_sm [64][132] = 8448 | wsm [16][1036] = 16576
#define WROW 1036                       // floats per og row (4144 B: 4096 + 48 pad)
#define KMAIN_SMEM ((8448 + 16 * WROW) * 4)   // 100096 B

// ---------------------------------------------------------------------------
// PTX helpers
// ---------------------------------------------------------------------------
__device__ __forceinline__ unsigned smaddr(const void* p) {
    return (unsigned)__cvta_generic_to_shared(p);
}
__device__ __forceinline__ void cpa16(unsigned d, const void* s) {
    asm volatile("cp.async.cg.shared.global [%0], [%1], 16;" :: "r"(d), "l"(s) : "memory");
}
__device__ __forceinline__ void cpa_commit() {
    asm volatile("cp.async.commit_group;" ::: "memory");
}
__device__ __forceinline__ void cpa_wait0() {
    asm volatile("cp.async.wait_group 0;" ::: "memory");
}

// ---------------------------------------------------------------------------
// Kernel 1: NCHW -> NHWC transpose
// ---------------------------------------------------------------------------
__global__ void k_transpose(const float* __restrict__ x) {
    __shared__ float tile[32][33];
    int bh = blockIdx.x;
    int b = bh >> 6, h = bh & 63;
    int c0 = blockIdx.y * 32;
    int w0 = blockIdx.z * 32;
    int tx = threadIdx.x, ty = threadIdx.y;
#pragma unroll
    for (int q = 0; q < 4; q++) {
        int c = c0 + ty + 8 * q;
        tile[ty + 8 * q][tx] = x[(((b * NC + c) * NH + h) * NW) + w0 + tx];
    }
    __syncthreads();
#pragma unroll
    for (int q = 0; q < 4; q++) {
        int w = w0 + ty + 8 * q;
        g_xt[((b * NH + h) * NW + w) * NC + c0 + tx] = tile[tx][ty + 8 * q];
    }
}

// ---------------------------------------------------------------------------
// Kernel 2: w[o][c][k] -> g_wt3[k][og][cp][m][e]
//   o = og*8 + m*2 + (e>>1),  c = 2*cp + (e&1)
// so each 8-byte pair = (even ch, odd ch) weights of one output.
// ---------------------------------------------------------------------------
__global__ void k_wt3(const float* __restrict__ w) {
    int i = blockIdx.x * 256 + threadIdx.x;
    if (i < 9 * 16384) {
        int k = i / 16384;
        int r = i & 16383;
        int ogw = r >> 10;
        int r2 = r & 1023;
        int cp = r2 >> 4;
        int e16 = r2 & 15;
        int m = e16 >> 2, e = e16 & 3;
        int o = ogw * 8 + m * 2 + (e >> 1);
        int c = 2 * cp + (e & 1);
        g_wt3[i] = w[(o * NC + c) * 9 + k];
    }
}

// ---------------------------------------------------------------------------
// Kernel 3: offset conv -> g_off (proven correct since R1)
// ---------------------------------------------------------------------------
__global__ void __launch_bounds__(256) k_off(const float* __restrict__ w_off,
                                             const float* __restrict__ b_off) {
    float* xin = dsm;                  // [3][64][128]
    float* sw  = dsm + 3 * NW * NC;    // [4][9][128]
    int h = blockIdx.x, b = blockIdx.y;
    int t = threadIdx.x;

    for (int r = 0; r < 3; r++) {
        int hr = h + r - 1;
        float4* dst = (float4*)(xin + r * NW * NC);
        if (hr >= 0 && hr < NH) {
            const float4* src = (const float4*)(g_xt + ((b * NH + hr) * NW) * NC);
            for (int i = t; i < (NW * NC) / 4; i += 256) dst[i] = src[i];
        } else {
            for (int i = t; i < (NW * NC) / 4; i += 256) dst[i] = make_float4(0.f, 0.f, 0.f, 0.f);
        }
    }
    for (int i = t; i < 4 * 9 * NC; i += 256) {
        int j = i / (9 * NC);
        int r2 = i % (9 * NC);
        int tap = r2 >> 7, c = r2 & 127;
        sw[i] = w_off[(j * NC + c) * 9 + tap];
    }
    __syncthreads();

    int wid = t >> 5, lane = t & 31;
    for (int it = 0; it < 8; it++) {
        int p = it * 8 + wid;
        float a0 = 0.f, a1 = 0.f, a2 = 0.f, a3 = 0.f;
#pragma unroll
        for (int tap = 0; tap < 9; tap++) {
            int dx = tap % 3 - 1;
            int dy = tap / 3;
            int xx = p + dx;
            if (xx < 0 || xx >= NW) continue;
            float4 xv = *(const float4*)(xin + (dy * NW + xx) * NC + lane * 4);
            float4 w0 = *(const float4*)(sw + (0 * 9 + tap) * NC + lane * 4);
            float4 w1 = *(const float4*)(sw + (1 * 9 + tap) * NC + lane * 4);
            float4 w2 = *(const float4*)(sw + (2 * 9 + tap) * NC + lane * 4);
            float4 w3 = *(const float4*)(sw + (3 * 9 + tap) * NC + lane * 4);
            a0 += xv.x * w0.x + xv.y * w0.y + xv.z * w0.z + xv.w * w0.w;
            a1 += xv.x * w1.x + xv.y * w1.y + xv.z * w1.z + xv.w * w1.w;
            a2 += xv.x * w2.x + xv.y * w2.y + xv.z * w2.z + xv.w * w2.w;
            a3 += xv.x * w3.x + xv.y * w3.y + xv.z * w3.z + xv.w * w3.w;
        }
#pragma unroll
        for (int off = 16; off; off >>= 1) {
            a0 += __shfl_xor_sync(0xffffffffu, a0, off);
            a1 += __shfl_xor_sync(0xffffffffu, a1, off);
            a2 += __shfl_xor_sync(0xffffffffu, a2, off);
            a3 += __shfl_xor_sync(0xffffffffu, a3, off);
        }
        if (lane == 0) {
            float sy = a0 + b_off[0];
            float sx = a1 + b_off[1];
            float s1 = fmaxf(a2 + b_off[2], 0.f) + 1.f;
            float s2 = fmaxf(a3 + b_off[3], 0.f) + 1.f;
            *(float4*)(g_off + ((b * NH + h) * NW + p) * 4) = make_float4(sy, sx, s1, s2);
        }
    }
}

// ---------------------------------------------------------------------------
// Kernel 4: deformable conv, conventional phased pipeline.
// grid (NH, NB): CTA = one (b,h) row, 64 px x 128 outs, 256 threads, 2 CTA/SM.
// Per tap:  cp.async weights (64KB, [og][cp] padded rows)
//         + sampling (warp-per-8px, lane = channel quad, recomputed corner math)
//         | syncthreads |
//         + GEMM: thread = 4px x 8outs, channel-paired f32x2 accumulators.
// ---------------------------------------------------------------------------
__global__ void __launch_bounds__(256, 2) k_main(const float* __restrict__ bias,
                                                 float* __restrict__ out) {
    float* s_sm = dsm;              // [64 px][132]
    float* wsm  = dsm + 8448;       // [16 og][1036]

    int h = blockIdx.x, b = blockIdx.y;
    int t = threadIdx.x;
    int wid = t >> 5, lane = t & 31;
    int og = t & 15, pxg = t >> 4;

    // per-lane pixel params: lane L holds px = wid*8 + (L&7)
    int mypx = wid * 8 + (lane & 7);
    float4 pr = *(const float4*)(g_off + ((b * NH + h) * NW + mypx) * 4);
    const float* xb = g_xt + (size_t)b * (NH * NW * NC);

    unsigned long long acc[32];
#pragma unroll
    for (int i = 0; i < 32; i++) acc[i] = 0ull;

    for (int k = 0; k < 9; k++) {
        if (k) __syncthreads();     // previous GEMM done -> buffers free

        // ---- weight tile: cp.async 64KB, thread t copies 256B contiguous ----
        {
            const float* src = g_wt3 + k * 16384 + t * 64;
#pragma unroll
            for (int q = 0; q < 16; q++) {
                int l = t * 16 + q;
                int ogw = l >> 8;
                int rem = l & 255;
                int cp = rem >> 2, m = rem & 3;
                cpa16(smaddr(wsm + ogw * WROW + cp * 16 + m * 4), src + q * 4);
            }
            cpa_commit();
        }

        // ---- sampling: warp handles px wid*8 .. wid*8+7, lane = channel quad ----
        float byk = c_BY[k], bxk = c_BX[k];
#pragma unroll 2
        for (int i = 0; i < 8; i++) {
            int px = wid * 8 + i;
            float sy = __shfl_sync(0xffffffffu, pr.x, i, 8);
            float sx = __shfl_sync(0xffffffffu, pr.y, i, 8);
            float s1 = __shfl_sync(0xffffffffu, pr.z, i, 8);
            float s2 = __shfl_sync(0xffffffffu, pr.w, i, 8);
            float sc = (k & 1) ? s2 : s1;
            float py  = (float)h  + byk * sc + sy;
            float pxf = (float)px + bxk * sc + sx;
            float y0f = floorf(py), x0f = floorf(pxf);
            float wy = py - y0f, wx = pxf - x0f;
            int y0 = (int)y0f, x0 = (int)x0f;
            int y1 = y0 + 1, x1 = x0 + 1;
            float w00 = (1.f - wy) * (1.f - wx);
            float w01 = (1.f - wy) * wx;
            float w10 = wy * (1.f - wx);
            float w11 = wy * wx;
            bool vy0 = (y0 >= 0) && (y0 < NH), vy1 = (y1 >= 0) && (y1 < NH);
            bool vx0 = (x0 >= 0) && (x0 < NW), vx1 = (x1 >= 0) && (x1 < NW);
            w00 = (vy0 && vx0) ? w00 : 0.f;
            w01 = (vy0 && vx1) ? w01 : 0.f;
            w10 = (vy1 && vx0) ? w10 : 0.f;
            w11 = (vy1 && vx1) ? w11 : 0.f;
            int cy0 = min(max(y0, 0), NH - 1), cy1 = min(max(y1, 0), NH - 1);
            int cx0 = min(max(x0, 0), NW - 1), cx1 = min(max(x1, 0), NW - 1);
            const float* p00 = xb + (cy0 * NW + cx0) * NC + lane * 4;
            const float* p01 = xb + (cy0 * NW + cx1) * NC + lane * 4;
            const float* p10 = xb + (cy1 * NW + cx0) * NC + lane * 4;
            const float* p11 = xb + (cy1 * NW + cx1) * NC + lane * 4;
            float4 v00 = *(const float4*)p00;
            float4 v01 = *(const float4*)p01;
            float4 v10 = *(const float4*)p10;
            float4 v11 = *(const float4*)p11;
            float4 s;
            s.x = w00 * v00.x + w01 * v01.x + w10 * v10.x + w11 * v11.x;
            s.y = w00 * v00.y + w01 * v01.y + w10 * v10.y + w11 * v11.y;
            s.z = w00 * v00.z + w01 * v01.z + w10 * v10.z + w11 * v11.z;
            s.w = w00 * v00.w + w01 * v01.w + w10 * v10.w + w11 * v11.w;
            *(float4*)(s_sm + px * 132 + lane * 4) = s;
        }
        cpa_wait0();
        __syncthreads();            // samples + weights visible

        // ---- GEMM: 32 chunks of 4 channels ----
        const float* abase = s_sm + pxg * 4 * 132;
        const float* wbase = wsm + og * WROW;
#pragma unroll 4
        for (int c4 = 0; c4 < 32; c4++) {
            unsigned long long aA[4], aB[4];
#pragma unroll
            for (int i = 0; i < 4; i++) {
                ulonglong2 av = *(const ulonglong2*)(abase + i * 132 + c4 * 4);
                aA[i] = av.x;       // channels (4c4, 4c4+1)   = cp 2c4
                aB[i] = av.y;       // channels (4c4+2, 4c4+3) = cp 2c4+1
            }
            const float* wp = wbase + c4 * 32;
            {   // cp = 2*c4
                ulonglong2 q0 = ((const ulonglong2*)wp)[0];
                ulonglong2 q1 = ((const ulonglong2*)wp)[1];
                ulonglong2 q2 = ((const ulonglong2*)wp)[2];
                ulonglong2 q3 = ((const ulonglong2*)wp)[3];
                unsigned long long wv[8] = {q0.x, q0.y, q1.x, q1.y,
                                            q2.x, q2.y, q3.x, q3.y};
#pragma unroll
                for (int i = 0; i < 4; i++)
#pragma unroll
                    for (int o = 0; o < 8; o++)
                        asm("fma.rn.f32x2 %0, %1, %2, %0;"
                            : "+l"(acc[i * 8 + o]) : "l"(wv[o]), "l"(aA[i]));
            }
            {   // cp = 2*c4 + 1
                const float* wq = wp + 16;
                ulonglong2 q0 = ((const ulonglong2*)wq)[0];
                ulonglong2 q1 = ((const ulonglong2*)wq)[1];
                ulonglong2 q2 = ((const ulonglong2*)wq)[2];
                ulonglong2 q3 = ((const ulonglong2*)wq)[3];
                unsigned long long wv[8] = {q0.x, q0.y, q1.x, q1.y,
                                            q2.x, q2.y, q3.x, q3.y};
#pragma unroll
                for (int i = 0; i < 4; i++)
#pragma unroll
                    for (int o = 0; o < 8; o++)
                        asm("fma.rn.f32x2 %0, %1, %2, %0;"
                            : "+l"(acc[i * 8 + o]) : "l"(wv[o]), "l"(aB[i]));
            }
        }
    }

    // ---- epilogue: direct STG.128 (lo+hi combine = even+odd channel sums) ----
#pragma unroll
    for (int o = 0; o < 8; o++) {
        float bv = __ldg(bias + og * 8 + o);
        float v[4];
#pragma unroll
        for (int i = 0; i < 4; i++) {
            float lo, hi;
            asm("mov.b64 {%0, %1}, %2;" : "=f"(lo), "=f"(hi) : "l"(acc[i * 8 + o]));
            v[i] = lo + hi + bv;
        }
        float* op = out + (((size_t)b * NC + og * 8 + o) * NH + h) * NW + pxg * 4;
        *(float4*)op = make_float4(v[0], v[1], v[2], v[3]);
    }
}

// ---------------------------------------------------------------------------
extern "C" void kernel_launch(void* const* d_in, const int* in_sizes, int n_in,
                              void* d_out, int out_size) {
    const float* x     = (const float*)d_in[0];
    const float* w_off = (const float*)d_in[1];
    const float* b_off = (const float*)d_in[2];
    const float* w     = (const float*)d_in[3];
    const float* bias  = (const float*)d_in[4];
    float* out = (float*)d_out;

    k_transpose<<<dim3(NB * NH, NC / 32, NW / 32), dim3(32, 8)>>>(x);
    k_wt3<<<(9 * 16384 + 255) / 256, 256>>>(w);

    int off_smem = (3 * NW * NC + 4 * 9 * NC) * (int)sizeof(float);   // 116 KB
    cudaFuncSetAttribute(k_off, cudaFuncAttributeMaxDynamicSharedMemorySize, off_smem);
    k_off<<<dim3(NH, NB), 256, off_smem>>>(w_off, b_off);

    cudaFuncSetAttribute(k_main, cudaFuncAttributeMaxDynamicSharedMemorySize, KMAIN_SMEM);
    k_main<<<dim3(NH, NB), 256, KMAIN_SMEM>>>(bias, out);
}

// round 13
// speedup vs baseline: 1.8602x; 1.1239x over previous
#include <cuda_runtime.h>

// Problem constants: B=8, CIN=COUT=128, H=W=64
#define NB   8
#define NC   128
#define NH   64
#define NW   64

// Scratch (device globals — no allocation allowed)
__device__ __align__(16) float g_xt[NB * NH * NW * NC];   // NHWC input, 16 MB
__device__ __align__(16) float g_off[NB * NH * NW * 4];   // shift_y, shift_x, scale1, scale2
__device__ __align__(16) float g_wt4[9 * 32 * 524];       // [k][og32][524]: padded smem image

__constant__ float c_BY[9] = {-1,-1,-1, 0,0,0, 1,1,1};
__constant__ float c_BX[9] = {-1, 0, 1,-1,0,1,-1,0,1};

extern __shared__ float dsm[];

// k_main smem: A0 [64][132]=8448 | A1 8448 | W [16][524]=8384  -> 25280 floats (101120 B)
#define WROW 524
#define KMAIN_SMEM (25280 * 4)

// ---------------------------------------------------------------------------
// PTX helpers
// ---------------------------------------------------------------------------
__device__ __forceinline__ unsigned smaddr(const void* p) {
    return (unsigned)__cvta_generic_to_shared(p);
}
__device__ __forceinline__ void cpa16(unsigned d, const void* s) {
    asm volatile("cp.async.cg.shared.global [%0], [%1], 16;" :: "r"(d), "l"(s) : "memory");
}
__device__ __forceinline__ void cpa_commit() {
    asm volatile("cp.async.commit_group;" ::: "memory");
}
__device__ __forceinline__ void cpa_wait0() {
    asm volatile("cp.async.wait_group 0;" ::: "memory");
}

// ---------------------------------------------------------------------------
// Kernel 1: NCHW -> NHWC transpose
// ---------------------------------------------------------------------------
__global__ void k_transpose(const float* __restrict__ x) {
    __shared__ float tile[32][33];
    int bh = blockIdx.x;
    int b = bh >> 6, h = bh & 63;
    int c0 = blockIdx.y * 32;
    int w0 = blockIdx.z * 32;
    int tx = threadIdx.x, ty = threadIdx.y;
#pragma unroll
    for (int q = 0; q < 4; q++) {
        int c = c0 + ty + 8 * q;
        tile[ty + 8 * q][tx] = x[(((b * NC + c) * NH + h) * NW) + w0 + tx];
    }
    __syncthreads();
#pragma unroll
    for (int q = 0; q < 4; q++) {
        int w = w0 + ty + 8 * q;
        g_xt[((b * NH + h) * NW + w) * NC + c0 + tx] = tile[tx][ty + 8 * q];
    }
}

// ---------------------------------------------------------------------------
// Kernel 2: w[o][c][k] -> g_wt4[k][og][e] padded rows of 524.
//   e<512: c4=e>>4, half=(e>>3)&1, o2=(e>>1)&3, j=e&1
//   o = og*4+o2, c = c4*4 + half*2 + j
// ---------------------------------------------------------------------------
__global__ void k_wt4(const float* __restrict__ w) {
    int i = blockIdx.x * 256 + threadIdx.x;
    if (i >= 9 * 32 * WROW) return;
    int k = i / (32 * WROW);
    int r = i % (32 * WROW);
    int og = r / WROW;
    int e = r % WROW;
    float val = 0.f;
    if (e < 512) {
        int c4 = e >> 4;
        int half = (e >> 3) & 1;
        int o2 = (e >> 1) & 3;
        int j = e & 1;
        int o = og * 4 + o2;
        int c = c4 * 4 + half * 2 + j;
        val = w[(o * NC + c) * 9 + k];
    }
    g_wt4[i] = val;
}

// ---------------------------------------------------------------------------
// Kernel 3: offset conv -> g_off (proven correct since R1)
// ---------------------------------------------------------------------------
__global__ void __launch_bounds__(256) k_off(const float* __restrict__ w_off,
                                             const float* __restrict__ b_off) {
    float* xin = dsm;                  // [3][64][128]
    float* sw  = dsm + 3 * NW * NC;    // [4][9][128]
    int h = blockIdx.x, b = blockIdx.y;
    int t = threadIdx.x;

    for (int r = 0; r < 3; r++) {
        int hr = h + r - 1;
        float4* dst = (float4*)(xin + r * NW * NC);
        if (hr >= 0 && hr < NH) {
            const float4* src = (const float4*)(g_xt + ((b * NH + hr) * NW) * NC);
            for (int i = t; i < (NW * NC) / 4; i += 256) dst[i] = src[i];
        } else {
            for (int i = t; i < (NW * NC) / 4; i += 256) dst[i] = make_float4(0.f, 0.f, 0.f, 0.f);
        }
    }
    for (int i = t; i < 4 * 9 * NC; i += 256) {
        int j = i / (9 * NC);
        int r2 = i % (9 * NC);
        int tap = r2 >> 7, c = r2 & 127;
        sw[i] = w_off[(j * NC + c) * 9 + tap];
    }
    __syncthreads();

    int wid = t >> 5, lane = t & 31;
    for (int it = 0; it < 8; it++) {
        int p = it * 8 + wid;
        float a0 = 0.f, a1 = 0.f, a2 = 0.f, a3 = 0.f;
#pragma unroll
        for (int tap = 0; tap < 9; tap++) {
            int dx = tap % 3 - 1;
            int dy = tap / 3;
            int xx = p + dx;
            if (xx < 0 || xx >= NW) continue;
            float4 xv = *(const float4*)(xin + (dy * NW + xx) * NC + lane * 4);
            float4 w0 = *(const float4*)(sw + (0 * 9 + tap) * NC + lane * 4);
            float4 w1 = *(const float4*)(sw + (1 * 9 + tap) * NC + lane * 4);
            float4 w2 = *(const float4*)(sw + (2 * 9 + tap) * NC + lane * 4);
            float4 w3 = *(const float4*)(sw + (3 * 9 + tap) * NC + lane * 4);
            a0 += xv.x * w0.x + xv.y * w0.y + xv.z * w0.z + xv.w * w0.w;
            a1 += xv.x * w1.x + xv.y * w1.y + xv.z * w1.z + xv.w * w1.w;
            a2 += xv.x * w2.x + xv.y * w2.y + xv.z * w2.z + xv.w * w2.w;
            a3 += xv.x * w3.x + xv.y * w3.y + xv.z * w3.z + xv.w * w3.w;
        }
#pragma unroll
        for (int off = 16; off; off >>= 1) {
            a0 += __shfl_xor_sync(0xffffffffu, a0, off);
            a1 += __shfl_xor_sync(0xffffffffu, a1, off);
            a2 += __shfl_xor_sync(0xffffffffu, a2, off);
            a3 += __shfl_xor_sync(0xffffffffu, a3, off);
        }
        if (lane == 0) {
            float sy = a0 + b_off[0];
            float sx = a1 + b_off[1];
            float s1 = fmaxf(a2 + b_off[2], 0.f) + 1.f;
            float s2 = fmaxf(a3 + b_off[3], 0.f) + 1.f;
            *(float4*)(g_off + ((b * NH + h) * NW + p) * 4) = make_float4(sy, sx, s1, s2);
        }
    }
}

// ---------------------------------------------------------------------------
// Bilinear sample of one pixel (j-th of this warp) for tap kk -> nbuf.
// Same math as R10 (proven).
// ---------------------------------------------------------------------------
__device__ __forceinline__ void samp(int kk, int j, float* nbuf, float4 pr,
                                     int wid, int lane, int h, const float* xb) {
    int px = wid * 8 + j;
    float sy = __shfl_sync(0xffffffffu, pr.x, j, 8);
    float sx = __shfl_sync(0xffffffffu, pr.y, j, 8);
    float s1 = __shfl_sync(0xffffffffu, pr.z, j, 8);
    float s2 = __shfl_sync(0xffffffffu, pr.w, j, 8);
    float sc = (kk & 1) ? s2 : s1;
    float py  = (float)h  + c_BY[kk] * sc + sy;
    float pxf = (float)px + c_BX[kk] * sc + sx;
    float y0f = floorf(py), x0f = floorf(pxf);
    float wy = py - y0f, wx = pxf - x0f;
    int y0 = (int)y0f, x0 = (int)x0f;
    int y1 = y0 + 1, x1 = x0 + 1;
    float w00 = (1.f - wy) * (1.f - wx);
    float w01 = (1.f - wy) * wx;
    float w10 = wy * (1.f - wx);
    float w11 = wy * wx;
    bool vy0 = (y0 >= 0) && (y0 < NH), vy1 = (y1 >= 0) && (y1 < NH);
    bool vx0 = (x0 >= 0) && (x0 < NW), vx1 = (x1 >= 0) && (x1 < NW);
    w00 = (vy0 && vx0) ? w00 : 0.f;
    w01 = (vy0 && vx1) ? w01 : 0.f;
    w10 = (vy1 && vx0) ? w10 : 0.f;
    w11 = (vy1 && vx1) ? w11 : 0.f;
    int cy0 = min(max(y0, 0), NH - 1), cy1 = min(max(y1, 0), NH - 1);
    int cx0 = min(max(x0, 0), NW - 1), cx1 = min(max(x1, 0), NW - 1);
    float4 v00 = *(const float4*)(xb + (cy0 * NW + cx0) * NC + lane * 4);
    float4 v01 = *(const float4*)(xb + (cy0 * NW + cx1) * NC + lane * 4);
    float4 v10 = *(const float4*)(xb + (cy1 * NW + cx0) * NC + lane * 4);
    float4 v11 = *(const float4*)(xb + (cy1 * NW + cx1) * NC + lane * 4);
    float4 s;
    s.x = w00 * v00.x + w01 * v01.x + w10 * v10.x + w11 * v11.x;
    s.y = w00 * v00.y + w01 * v01.y + w10 * v10.y + w11 * v11.y;
    s.z = w00 * v00.z + w01 * v01.z + w10 * v10.z + w11 * v11.z;
    s.w = w00 * v00.w + w01 * v01.w + w10 * v10.w + w11 * v11.w;
    *(float4*)(nbuf + px * 132 + lane * 4) = s;
}

// ---------------------------------------------------------------------------
// Kernel 4: deformable conv, sampling software-pipelined into the GEMM.
// grid (NH, NB, 2): CTA = (b,h) row x out-half z, 64 px x 64 outs, 256 thr,
// 2 CTAs/SM. A tile double-buffered; tap-(k+1) sampling interleaved into
// tap-k GEMM (1 px per 4 c4-chunks). Thread = 4 px x 4 outs, channel-paired
// f32x2 accumulators.
// ---------------------------------------------------------------------------
__global__ void __launch_bounds__(256, 2) k_main(const float* __restrict__ bias,
                                                 float* __restrict__ out) {
    float* Ab0 = dsm;              // [64][132]
    float* Ab1 = dsm + 8448;
    float* wsm = dsm + 16896;      // [16 og][524]

    int h = blockIdx.x, b = blockIdx.y, z = blockIdx.z;
    int t = threadIdx.x;
    int wid = t >> 5, lane = t & 31;
    int og = t & 15, pxg = t >> 4;

    int mypx = wid * 8 + (lane & 7);
    float4 pr = *(const float4*)(g_off + ((b * NH + h) * NW + mypx) * 4);
    const float* xb = g_xt + (size_t)b * (NH * NW * NC);

    unsigned long long acc[16];
#pragma unroll
    for (int i = 0; i < 16; i++) acc[i] = 0ull;

    // prologue: sample tap 0 into Ab0
#pragma unroll 2
    for (int j = 0; j < 8; j++) samp(0, j, Ab0, pr, wid, lane, h, xb);

    for (int k = 0; k < 9; k++) {
        __syncthreads();           // prev GEMM done: W + next A buffer free

        // W tile for this tap: linear cp.async of 16 padded og rows (33.5 KB)
        {
            const float* wsrc = g_wt4 + ((size_t)k * 32 + z * 16) * WROW;
            for (int i = t; i < (16 * WROW) / 4; i += 256)
                cpa16(smaddr(wsm + i * 4), wsrc + i * 4);
            cpa_commit();
        }

        float* nbuf = (k & 1) ? Ab0 : Ab1;          // tap k+1 buffer
        const float* cbuf = (k & 1) ? Ab1 : Ab0;    // tap k buffer
        bool dos = (k < 8);
        if (dos) {
            samp(k + 1, 0, nbuf, pr, wid, lane, h, xb);
            samp(k + 1, 1, nbuf, pr, wid, lane, h, xb);
        }
        cpa_wait0();
        __syncthreads();           // W visible to all warps

        const float* abase = cbuf + pxg * 4 * 132;
        const float* wrow = wsm + og * WROW;
#pragma unroll 2
        for (int seg = 0; seg < 8; seg++) {
            if (dos && seg < 6) samp(k + 1, seg + 2, nbuf, pr, wid, lane, h, xb);
#pragma unroll
            for (int cq = 0; cq < 4; cq++) {
                int c4 = seg * 4 + cq;
                unsigned long long aA[4], aB[4];
#pragma unroll
                for (int i = 0; i < 4; i++) {
                    ulonglong2 av = *(const ulonglong2*)(abase + i * 132 + c4 * 4);
                    aA[i] = av.x;      // channels 4c4, 4c4+1
                    aB[i] = av.y;      // channels 4c4+2, 4c4+3
                }
                const float* wp = wrow + c4 * 16;
                ulonglong2 we0 = ((const ulonglong2*)wp)[0];
                ulonglong2 we1 = ((const ulonglong2*)wp)[1];
                ulonglong2 wo0 = ((const ulonglong2*)wp)[2];
                ulonglong2 wo1 = ((const ulonglong2*)wp)[3];
                unsigned long long wE[4] = {we0.x, we0.y, we1.x, we1.y};
                unsigned long long wO[4] = {wo0.x, wo0.y, wo1.x, wo1.y};
#pragma unroll
                for (int i = 0; i < 4; i++)
#pragma unroll
                    for (int o = 0; o < 4; o++) {
                        asm("fma.rn.f32x2 %0, %1, %2, %0;"
                            : "+l"(acc[i * 4 + o]) : "l"(wE[o]), "l"(aA[i]));
                        asm("fma.rn.f32x2 %0, %1, %2, %0;"
                            : "+l"(acc[i * 4 + o]) : "l"(wO[o]), "l"(aB[i]));
                    }
            }
        }
    }

    // ---- epilogue: direct STG.128 ----
#pragma unroll
    for (int oi = 0; oi < 4; oi++) {
        int o = z * 64 + og * 4 + oi;
        float bv = __ldg(bias + o);
        float v[4];
#pragma unroll
        for (int i = 0; i < 4; i++) {
            float lo, hi;
            asm("mov.b64 {%0, %1}, %2;" : "=f"(lo), "=f"(hi) : "l"(acc[i * 4 + oi]));
            v[i] = lo + hi + bv;
        }
        float* op = out + (((size_t)b * NC + o) * NH + h) * NW + pxg * 4;
        *(float4*)op = make_float4(v[0], v[1], v[2], v[3]);
    }
}

// ---------------------------------------------------------------------------
extern "C" void kernel_launch(void* const* d_in, const int* in_sizes, int n_in,
                              void* d_out, int out_size) {
    const float* x     = (const float*)d_in[0];
    const float* w_off = (const float*)d_in[1];
    const float* b_off = (const float*)d_in[2];
    const float* w     = (const float*)d_in[3];
    const float* bias  = (const float*)d_in[4];
    float* out = (float*)d_out;

    k_transpose<<<dim3(NB * NH, NC / 32, NW / 32), dim3(32, 8)>>>(x);
    k_wt4<<<(9 * 32 * WROW + 255) / 256, 256>>>(w);

    int off_smem = (3 * NW * NC + 4 * 9 * NC) * (int)sizeof(float);   // 116 KB
    cudaFuncSetAttribute(k_off, cudaFuncAttributeMaxDynamicSharedMemorySize, off_smem);
    k_off<<<dim3(NH, NB), 256, off_smem>>>(w_off, b_off);

    cudaFuncSetAttribute(k_main, cudaFuncAttributeMaxDynamicSharedMemorySize, KMAIN_SMEM);
    k_main<<<dim3(NH, NB, 2), 256, KMAIN_SMEM>>>(bias, out);
}

// round 14
// speedup vs baseline: 1.8827x; 1.0121x over previous
#include <cuda_runtime.h>

// Problem constants: B=8, CIN=COUT=128, H=W=64
#define NB   8
#define NC   128
#define NH   64
#define NW   64

// Scratch (device globals — no allocation allowed)
__device__ __align__(16) float g_xt[NB * NH * NW * NC];   // NHWC input, 16 MB
__device__ __align__(16) float g_off[NB * NH * NW * 4];   // shift_y, shift_x, scale1, scale2
__device__ __align__(16) float g_wt5[9 * 2 * 8 * 1028];   // [k][z][og8][1028] smem image

__constant__ float c_BY[9] = {-1,-1,-1, 0,0,0, 1,1,1};
__constant__ float c_BX[9] = {-1, 0, 1,-1,0,1,-1,0,1};

extern __shared__ float dsm[];

// k_main smem: A0 [64][132]=8448 | A1 8448 | W [8 og][1028]=8224  -> 25120 floats
#define WROW 1028
#define KMAIN_SMEM (25120 * 4)

// ---------------------------------------------------------------------------
// PTX helpers
// ---------------------------------------------------------------------------
__device__ __forceinline__ unsigned smaddr(const void* p) {
    return (unsigned)__cvta_generic_to_shared(p);
}
__device__ __forceinline__ void cpa16(unsigned d, const void* s) {
    asm volatile("cp.async.cg.shared.global [%0], [%1], 16;" :: "r"(d), "l"(s) : "memory");
}
__device__ __forceinline__ void cpa_commit() {
    asm volatile("cp.async.commit_group;" ::: "memory");
}
__device__ __forceinline__ void cpa_wait0() {
    asm volatile("cp.async.wait_group 0;" ::: "memory");
}

// ---------------------------------------------------------------------------
// Kernel 1: NCHW -> NHWC transpose
// ---------------------------------------------------------------------------
__global__ void k_transpose(const float* __restrict__ x) {
    __shared__ float tile[32][33];
    int bh = blockIdx.x;
    int b = bh >> 6, h = bh & 63;
    int c0 = blockIdx.y * 32;
    int w0 = blockIdx.z * 32;
    int tx = threadIdx.x, ty = threadIdx.y;
#pragma unroll
    for (int q = 0; q < 4; q++) {
        int c = c0 + ty + 8 * q;
        tile[ty + 8 * q][tx] = x[(((b * NC + c) * NH + h) * NW) + w0 + tx];
    }
    __syncthreads();
#pragma unroll
    for (int q = 0; q < 4; q++) {
        int w = w0 + ty + 8 * q;
        g_xt[((b * NH + h) * NW + w) * NC + c0 + tx] = tile[tx][ty + 8 * q];
    }
}

// ---------------------------------------------------------------------------
// Kernel 2: weight smem image.
// g_wt5[k][z][og3][e], e<1024: c4=e>>5, pair=(e>>4)&1, ou=(e>>1)&7, j=e&1
//   o = z*64 + og3*8 + ou,  c = c4*4 + pair*2 + j
// ---------------------------------------------------------------------------
__global__ void k_wt5(const float* __restrict__ w) {
    int i = blockIdx.x * 256 + threadIdx.x;
    const int PER = 8 * WROW;          // 8224 per (k,z)
    if (i >= 9 * 2 * PER) return;
    int kz = i / PER;
    int r = i % PER;
    int k = kz >> 1, z = kz & 1;
    int og3 = r / WROW;
    int e = r % WROW;
    float val = 0.f;
    if (e < 1024) {
        int c4 = e >> 5;
        int pair = (e >> 4) & 1;
        int ou = (e >> 1) & 7;
        int j = e & 1;
        int o = z * 64 + og3 * 8 + ou;
        int c = c4 * 4 + pair * 2 + j;
        val = w[(o * NC + c) * 9 + k];
    }
    g_wt5[i] = val;
}

// ---------------------------------------------------------------------------
// Kernel 3: offset conv -> g_off (proven correct since R1)
// ---------------------------------------------------------------------------
__global__ void __launch_bounds__(256) k_off(const float* __restrict__ w_off,
                                             const float* __restrict__ b_off) {
    float* xin = dsm;                  // [3][64][128]
    float* sw  = dsm + 3 * NW * NC;    // [4][9][128]
    int h = blockIdx.x, b = blockIdx.y;
    int t = threadIdx.x;

    for (int r = 0; r < 3; r++) {
        int hr = h + r - 1;
        float4* dst = (float4*)(xin + r * NW * NC);
        if (hr >= 0 && hr < NH) {
            const float4* src = (const float4*)(g_xt + ((b * NH + hr) * NW) * NC);
            for (int i = t; i < (NW * NC) / 4; i += 256) dst[i] = src[i];
        } else {
            for (int i = t; i < (NW * NC) / 4; i += 256) dst[i] = make_float4(0.f, 0.f, 0.f, 0.f);
        }
    }
    for (int i = t; i < 4 * 9 * NC; i += 256) {
        int j = i / (9 * NC);
        int r2 = i % (9 * NC);
        int tap = r2 >> 7, c = r2 & 127;
        sw[i] = w_off[(j * NC + c) * 9 + tap];
    }
    __syncthreads();

    int wid = t >> 5, lane = t & 31;
    for (int it = 0; it < 8; it++) {
        int p = it * 8 + wid;
        float a0 = 0.f, a1 = 0.f, a2 = 0.f, a3 = 0.f;
#pragma unroll
        for (int tap = 0; tap < 9; tap++) {
            int dx = tap % 3 - 1;
            int dy = tap / 3;
            int xx = p + dx;
            if (xx < 0 || xx >= NW) continue;
            float4 xv = *(const float4*)(xin + (dy * NW + xx) * NC + lane * 4);
            float4 w0 = *(const float4*)(sw + (0 * 9 + tap) * NC + lane * 4);
            float4 w1 = *(const float4*)(sw + (1 * 9 + tap) * NC + lane * 4);
            float4 w2 = *(const float4*)(sw + (2 * 9 + tap) * NC + lane * 4);
            float4 w3 = *(const float4*)(sw + (3 * 9 + tap) * NC + lane * 4);
            a0 += xv.x * w0.x + xv.y * w0.y + xv.z * w0.z + xv.w * w0.w;
            a1 += xv.x * w1.x + xv.y * w1.y + xv.z * w1.z + xv.w * w1.w;
            a2 += xv.x * w2.x + xv.y * w2.y + xv.z * w2.z + xv.w * w2.w;
            a3 += xv.x * w3.x + xv.y * w3.y + xv.z * w3.z + xv.w * w3.w;
        }
#pragma unroll
        for (int off = 16; off; off >>= 1) {
            a0 += __shfl_xor_sync(0xffffffffu, a0, off);
            a1 += __shfl_xor_sync(0xffffffffu, a1, off);
            a2 += __shfl_xor_sync(0xffffffffu, a2, off);
            a3 += __shfl_xor_sync(0xffffffffu, a3, off);
        }
        if (lane == 0) {
            float sy = a0 + b_off[0];
            float sx = a1 + b_off[1];
            float s1 = fmaxf(a2 + b_off[2], 0.f) + 1.f;
            float s2 = fmaxf(a3 + b_off[3], 0.f) + 1.f;
            *(float4*)(g_off + ((b * NH + h) * NW + p) * 4) = make_float4(sy, sx, s1, s2);
        }
    }
}

// ---------------------------------------------------------------------------
// Bilinear sample of one pixel (j-th of this warp) for tap kk -> nbuf.
// Stores channel quad q at rotated column (q + px/8) mod 32 (bank spread).
// ---------------------------------------------------------------------------
__device__ __forceinline__ void samp(int kk, int j, float* nbuf, float4 pr,
                                     int wid, int lane, int h, const float* xb) {
    int px = wid * 8 + j;
    float sy = __shfl_sync(0xffffffffu, pr.x, j, 8);
    float sx = __shfl_sync(0xffffffffu, pr.y, j, 8);
    float s1 = __shfl_sync(0xffffffffu, pr.z, j, 8);
    float s2 = __shfl_sync(0xffffffffu, pr.w, j, 8);
    float sc = (kk & 1) ? s2 : s1;
    float py  = (float)h  + c_BY[kk] * sc + sy;
    float pxf = (float)px + c_BX[kk] * sc + sx;
    float y0f = floorf(py), x0f = floorf(pxf);
    float wy = py - y0f, wx = pxf - x0f;
    int y0 = (int)y0f, x0 = (int)x0f;
    int y1 = y0 + 1, x1 = x0 + 1;
    float w00 = (1.f - wy) * (1.f - wx);
    float w01 = (1.f - wy) * wx;
    float w10 = wy * (1.f - wx);
    float w11 = wy * wx;
    bool vy0 = (y0 >= 0) && (y0 < NH), vy1 = (y1 >= 0) && (y1 < NH);
    bool vx0 = (x0 >= 0) && (x0 < NW), vx1 = (x1 >= 0) && (x1 < NW);
    w00 = (vy0 && vx0) ? w00 : 0.f;
    w01 = (vy0 && vx1) ? w01 : 0.f;
    w10 = (vy1 && vx0) ? w10 : 0.f;
    w11 = (vy1 && vx1) ? w11 : 0.f;
    int cy0 = min(max(y0, 0), NH - 1), cy1 = min(max(y1, 0), NH - 1);
    int cx0 = min(max(x0, 0), NW - 1), cx1 = min(max(x1, 0), NW - 1);
    float4 v00 = *(const float4*)(xb + (cy0 * NW + cx0) * NC + lane * 4);
    float4 v01 = *(const float4*)(xb + (cy0 * NW + cx1) * NC + lane * 4);
    float4 v10 = *(const float4*)(xb + (cy1 * NW + cx0) * NC + lane * 4);
    float4 v11 = *(const float4*)(xb + (cy1 * NW + cx1) * NC + lane * 4);
    float4 s;
    s.x = w00 * v00.x + w01 * v01.x + w10 * v10.x + w11 * v11.x;
    s.y = w00 * v00.y + w01 * v01.y + w10 * v10.y + w11 * v11.y;
    s.z = w00 * v00.z + w01 * v01.z + w10 * v10.z + w11 * v11.z;
    s.w = w00 * v00.w + w01 * v01.w + w10 * v10.w + w11 * v11.w;
    int col = (lane + wid) & 31;
    *(float4*)(nbuf + px * 132 + col * 4) = s;
}

// ---------------------------------------------------------------------------
// Kernel 4: deformable conv, pipelined, channel-split GEMM.
// grid (NH, NB, 2): CTA = (b,h) row x out-half z. 256 thr, 2 CTA/SM.
// GEMM thread map: og3 = t&7 (8 outs), pg = (t>>3)&15 (4 px), cs = t>>7 (ch half).
// Thread tile 4px x 8out, channel-paired f32x2 acc (32 ull).
// Per 4-ch chunk: 4 A-LDS.128 (rotated, 1 wf) + 8 W-LDS.128 (1 wf) + 64 FFMA2.
// Epilogue: cs=1 stages partials in smem (stride 33), cs=0 adds + STG.128.
// ---------------------------------------------------------------------------
__global__ void __launch_bounds__(256, 2) k_main(const float* __restrict__ bias,
                                                 float* __restrict__ out) {
    float* Ab0 = dsm;              // [64][132]
    float* Ab1 = dsm + 8448;
    float* wsm = dsm + 16896;      // [8 og][1028]

    int h = blockIdx.x, b = blockIdx.y, z = blockIdx.z;
    int t = threadIdx.x;
    int wid = t >> 5, lane = t & 31;
    int og3 = t & 7;
    int pg = (t >> 3) & 15;
    int cs = t >> 7;
    int rot = pg >> 1;             // = px>>3 for this thread's 4 pixels

    int mypx = wid * 8 + (lane & 7);
    float4 pr = *(const float4*)(g_off + ((b * NH + h) * NW + mypx) * 4);
    const float* xb = g_xt + (size_t)b * (NH * NW * NC);

    unsigned long long acc[32];
#pragma unroll
    for (int i = 0; i < 32; i++) acc[i] = 0ull;

    // prologue: sample tap 0 into Ab0
#pragma unroll 2
    for (int j = 0; j < 8; j++) samp(0, j, Ab0, pr, wid, lane, h, xb);

    for (int k = 0; k < 9; k++) {
        __syncthreads();           // prev GEMM done: W + next A buffer free

        // W tile: linear cp.async of the 8-row smem image (32.9 KB)
        {
            const float* wsrc = g_wt5 + ((size_t)k * 2 + z) * (8 * WROW);
            for (int i = t; i < (8 * WROW) / 4; i += 256)
                cpa16(smaddr(wsm + i * 4), wsrc + i * 4);
            cpa_commit();
        }

        float* nbuf = (k & 1) ? Ab0 : Ab1;          // tap k+1 buffer
        const float* cbuf = (k & 1) ? Ab1 : Ab0;    // tap k buffer
        bool dos = (k < 8);
        if (dos) {
            samp(k + 1, 0, nbuf, pr, wid, lane, h, xb);
            samp(k + 1, 1, nbuf, pr, wid, lane, h, xb);
        }
        cpa_wait0();
        __syncthreads();           // W + samples visible

        const float* arow = cbuf + pg * 4 * 132;
        const float* wrow = wsm + og3 * WROW;
#pragma unroll 1
        for (int j = 0; j < 16; j++) {
            if (dos && j < 6) samp(k + 1, j + 2, nbuf, pr, wid, lane, h, xb);
            int c4 = cs * 16 + j;
            int col = (c4 + rot) & 31;
            unsigned long long aA[4], aB[4];
#pragma unroll
            for (int i = 0; i < 4; i++) {
                ulonglong2 av = *(const ulonglong2*)(arow + i * 132 + col * 4);
                aA[i] = av.x;      // channels 4c4, 4c4+1
                aB[i] = av.y;      // channels 4c4+2, 4c4+3
            }
            const float* wp = wrow + c4 * 32;
            {   // pair 0 (even/odd = ch 4c4, 4c4+1)
                ulonglong2 q0 = ((const ulonglong2*)wp)[0];
                ulonglong2 q1 = ((const ulonglong2*)wp)[1];
                ulonglong2 q2 = ((const ulonglong2*)wp)[2];
                ulonglong2 q3 = ((const ulonglong2*)wp)[3];
                unsigned long long wv[8] = {q0.x, q0.y, q1.x, q1.y,
                                            q2.x, q2.y, q3.x, q3.y};
#pragma unroll
                for (int i = 0; i < 4; i++)
#pragma unroll
                    for (int o = 0; o < 8; o++)
                        asm("fma.rn.f32x2 %0, %1, %2, %0;"
                            : "+l"(acc[i * 8 + o]) : "l"(wv[o]), "l"(aA[i]));
            }
            {   // pair 1 (ch 4c4+2, 4c4+3)
                const float* wq = wp + 16;
                ulonglong2 q0 = ((const ulonglong2*)wq)[0];
                ulonglong2 q1 = ((const ulonglong2*)wq)[1];
                ulonglong2 q2 = ((const ulonglong2*)wq)[2];
                ulonglong2 q3 = ((const ulonglong2*)wq)[3];
                unsigned long long wv[8] = {q0.x, q0.y, q1.x, q1.y,
                                            q2.x, q2.y, q3.x, q3.y};
#pragma unroll
                for (int i = 0; i < 4; i++)
#pragma unroll
                    for (int o = 0; o < 8; o++)
                        asm("fma.rn.f32x2 %0, %1, %2, %0;"
                            : "+l"(acc[i * 8 + o]) : "l"(wv[o]), "l"(aB[i]));
            }
        }
    }

    // ---- channel-split reduction + output ----
    float val[32];
#pragma unroll
    for (int e = 0; e < 32; e++) {
        float lo, hi;
        asm("mov.b64 {%0, %1}, %2;" : "=f"(lo), "=f"(hi) : "l"(acc[e]));
        val[e] = lo + hi;
    }
    __syncthreads();               // last GEMM reads done; A buffers reusable

    if (cs == 1) {                 // stage partials: slot stride 33 (odd) -> conflict-free
        int slot = t & 127;
#pragma unroll
        for (int e = 0; e < 32; e++) dsm[slot * 33 + e] = val[e];
    }
    __syncthreads();
    if (cs == 0) {
        int slot = t;
#pragma unroll
        for (int e = 0; e < 32; e++) val[e] += dsm[slot * 33 + e];
        // write: 8 outs x 4 px (STG.128 each)
#pragma unroll
        for (int o = 0; o < 8; o++) {
            int oo = z * 64 + og3 * 8 + o;
            float bv = __ldg(bias + oo);
            float* op = out + (((size_t)b * NC + oo) * NH + h) * NW + pg * 4;
            *(float4*)op = make_float4(val[0 * 8 + o] + bv, val[1 * 8 + o] + bv,
                                       val[2 * 8 + o] + bv, val[3 * 8 + o] + bv);
        }
    }
}

// ---------------------------------------------------------------------------
extern "C" void kernel_launch(void* const* d_in, const int* in_sizes, int n_in,
                              void* d_out, int out_size) {
    const float* x     = (const float*)d_in[0];
    const float* w_off = (const float*)d_in[1];
    const float* b_off = (const float*)d_in[2];
    const float* w     = (const float*)d_in[3];
    const float* bias  = (const float*)d_in[4];
    float* out = (float*)d_out;

    k_transpose<<<dim3(NB * NH, NC / 32, NW / 32), dim3(32, 8)>>>(x);
    k_wt5<<<(9 * 2 * 8 * WROW + 255) / 256, 256>>>(w);

    int off_smem = (3 * NW * NC + 4 * 9 * NC) * (int)sizeof(float);   // 116 KB
    cudaFuncSetAttribute(k_off, cudaFuncAttributeMaxDynamicSharedMemorySize, off_smem);
    k_off<<<dim3(NH, NB), 256, off_smem>>>(w_off, b_off);

    cudaFuncSetAttribute(k_main, cudaFuncAttributeMaxDynamicSharedMemorySize, KMAIN_SMEM);
    k_main<<<dim3(NH, NB, 2), 256, KMAIN_SMEM>>>(bias, out);
}

// round 15
// speedup vs baseline: 1.9178x; 1.0187x over previous
#include <cuda_runtime.h>

// Problem constants: B=8, CIN=COUT=128, H=W=64
#define NB   8
#define NC   128
#define NH   64
#define NW   64

// Scratch (device globals — no allocation allowed)
__device__ __align__(16) float g_xt[NB * NH * NW * NC];   // NHWC input, 16 MB
__device__ __align__(16) float g_off[NB * NH * NW * 4];   // shift_y, shift_x, scale1, scale2
__device__ __align__(16) float g_wt6[9 * 16 * 1028];      // [k][og16][1028] smem image

__constant__ float c_BY[9] = {-1,-1,-1, 0,0,0, 1,1,1};
__constant__ float c_BX[9] = {-1, 0, 1,-1,0,1,-1,0,1};

extern __shared__ float dsm[];

// k_main smem: A0 [32][132]=4224 | A1 4224 | W [16 og][1028]=16448 -> 24896 floats
#define WROW 1028
#define KMAIN_SMEM (24896 * 4)

// ---------------------------------------------------------------------------
// PTX helpers
// ---------------------------------------------------------------------------
__device__ __forceinline__ unsigned smaddr(const void* p) {
    return (unsigned)__cvta_generic_to_shared(p);
}
__device__ __forceinline__ void cpa16(unsigned d, const void* s) {
    asm volatile("cp.async.cg.shared.global [%0], [%1], 16;" :: "r"(d), "l"(s) : "memory");
}
__device__ __forceinline__ void cpa_commit() {
    asm volatile("cp.async.commit_group;" ::: "memory");
}
__device__ __forceinline__ void cpa_wait0() {
    asm volatile("cp.async.wait_group 0;" ::: "memory");
}

// ---------------------------------------------------------------------------
// Kernel 1: NCHW -> NHWC transpose
// ---------------------------------------------------------------------------
__global__ void k_transpose(const float* __restrict__ x) {
    __shared__ float tile[32][33];
    int bh = blockIdx.x;
    int b = bh >> 6, h = bh & 63;
    int c0 = blockIdx.y * 32;
    int w0 = blockIdx.z * 32;
    int tx = threadIdx.x, ty = threadIdx.y;
#pragma unroll
    for (int q = 0; q < 4; q++) {
        int c = c0 + ty + 8 * q;
        tile[ty + 8 * q][tx] = x[(((b * NC + c) * NH + h) * NW) + w0 + tx];
    }
    __syncthreads();
#pragma unroll
    for (int q = 0; q < 4; q++) {
        int w = w0 + ty + 8 * q;
        g_xt[((b * NH + h) * NW + w) * NC + c0 + tx] = tile[tx][ty + 8 * q];
    }
}

// ---------------------------------------------------------------------------
// Kernel 2: weight smem image. g_wt6[k][og][e], e<1024:
//   c4=e>>5, pair=(e>>4)&1, ou=(e>>1)&7, j=e&1
//   o = og*8 + ou,  c = c4*4 + pair*2 + j
// ---------------------------------------------------------------------------
__global__ void k_wt6(const float* __restrict__ w) {
    int i = blockIdx.x * 256 + threadIdx.x;
    const int PER = 16 * WROW;         // 16448 per k
    if (i >= 9 * PER) return;
    int k = i / PER;
    int r = i % PER;
    int og = r / WROW;
    int e = r % WROW;
    float val = 0.f;
    if (e < 1024) {
        int c4 = e >> 5;
        int pair = (e >> 4) & 1;
        int ou = (e >> 1) & 7;
        int j = e & 1;
        int o = og * 8 + ou;
        int c = c4 * 4 + pair * 2 + j;
        val = w[(o * NC + c) * 9 + k];
    }
    g_wt6[i] = val;
}

// ---------------------------------------------------------------------------
// Kernel 3: offset conv -> g_off (proven correct since R1)
// ---------------------------------------------------------------------------
__global__ void __launch_bounds__(256) k_off(const float* __restrict__ w_off,
                                             const float* __restrict__ b_off) {
    float* xin = dsm;                  // [3][64][128]
    float* sw  = dsm + 3 * NW * NC;    // [4][9][128]
    int h = blockIdx.x, b = blockIdx.y;
    int t = threadIdx.x;

    for (int r = 0; r < 3; r++) {
        int hr = h + r - 1;
        float4* dst = (float4*)(xin + r * NW * NC);
        if (hr >= 0 && hr < NH) {
            const float4* src = (const float4*)(g_xt + ((b * NH + hr) * NW) * NC);
            for (int i = t; i < (NW * NC) / 4; i += 256) dst[i] = src[i];
        } else {
            for (int i = t; i < (NW * NC) / 4; i += 256) dst[i] = make_float4(0.f, 0.f, 0.f, 0.f);
        }
    }
    for (int i = t; i < 4 * 9 * NC; i += 256) {
        int j = i / (9 * NC);
        int r2 = i % (9 * NC);
        int tap = r2 >> 7, c = r2 & 127;
        sw[i] = w_off[(j * NC + c) * 9 + tap];
    }
    __syncthreads();

    int wid = t >> 5, lane = t & 31;
    for (int it = 0; it < 8; it++) {
        int p = it * 8 + wid;
        float a0 = 0.f, a1 = 0.f, a2 = 0.f, a3 = 0.f;
#pragma unroll
        for (int tap = 0; tap < 9; tap++) {
            int dx = tap % 3 - 1;
            int dy = tap / 3;
            int xx = p + dx;
            if (xx < 0 || xx >= NW) continue;
            float4 xv = *(const float4*)(xin + (dy * NW + xx) * NC + lane * 4);
            float4 w0 = *(const float4*)(sw + (0 * 9 + tap) * NC + lane * 4);
            float4 w1 = *(const float4*)(sw + (1 * 9 + tap) * NC + lane * 4);
            float4 w2 = *(const float4*)(sw + (2 * 9 + tap) * NC + lane * 4);
            float4 w3 = *(const float4*)(sw + (3 * 9 + tap) * NC + lane * 4);
            a0 += xv.x * w0.x + xv.y * w0.y + xv.z * w0.z + xv.w * w0.w;
            a1 += xv.x * w1.x + xv.y * w1.y + xv.z * w1.z + xv.w * w1.w;
            a2 += xv.x * w2.x + xv.y * w2.y + xv.z * w2.z + xv.w * w2.w;
            a3 += xv.x * w3.x + xv.y * w3.y + xv.z * w3.z + xv.w * w3.w;
        }
#pragma unroll
        for (int off = 16; off; off >>= 1) {
            a0 += __shfl_xor_sync(0xffffffffu, a0, off);
            a1 += __shfl_xor_sync(0xffffffffu, a1, off);
            a2 += __shfl_xor_sync(0xffffffffu, a2, off);
            a3 += __shfl_xor_sync(0xffffffffu, a3, off);
        }
        if (lane == 0) {
            float sy = a0 + b_off[0];
            float sx = a1 + b_off[1];
            float s1 = fmaxf(a2 + b_off[2], 0.f) + 1.f;
            float s2 = fmaxf(a3 + b_off[3], 0.f) + 1.f;
            *(float4*)(g_off + ((b * NH + h) * NW + p) * 4) = make_float4(sy, sx, s1, s2);
        }
    }
}

// ---------------------------------------------------------------------------
// Split gather: samp_load issues corner math + 4 LDGs into registers;
// samp_store (>=4 GEMM chunks later) combines and writes the A tile.
// ---------------------------------------------------------------------------
struct GS {
    float4 v00, v01, v10, v11;
    float w00, w01, w10, w11;
    float* dst;
};

__device__ __forceinline__ void samp_load(int kk, int j, int half, GS& g,
                                          float4 pr, int wid, int lane, int h,
                                          const float* xb, float* nbuf) {
    int pxl = wid * 4 + j;             // local pixel 0..31
    int pw  = half * 32 + pxl;         // image w coordinate
    float sy = __shfl_sync(0xffffffffu, pr.x, j, 4);
    float sx = __shfl_sync(0xffffffffu, pr.y, j, 4);
    float s1 = __shfl_sync(0xffffffffu, pr.z, j, 4);
    float s2 = __shfl_sync(0xffffffffu, pr.w, j, 4);
    float sc = (kk & 1) ? s2 : s1;
    float py  = (float)h  + c_BY[kk] * sc + sy;
    float pxf = (float)pw + c_BX[kk] * sc + sx;
    float y0f = floorf(py), x0f = floorf(pxf);
    float wy = py - y0f, wx = pxf - x0f;
    int y0 = (int)y0f, x0 = (int)x0f;
    int y1 = y0 + 1, x1 = x0 + 1;
    float w00 = (1.f - wy) * (1.f - wx);
    float w01 = (1.f - wy) * wx;
    float w10 = wy * (1.f - wx);
    float w11 = wy * wx;
    bool vy0 = (y0 >= 0) && (y0 < NH), vy1 = (y1 >= 0) && (y1 < NH);
    bool vx0 = (x0 >= 0) && (x0 < NW), vx1 = (x1 >= 0) && (x1 < NW);
    g.w00 = (vy0 && vx0) ? w00 : 0.f;
    g.w01 = (vy0 && vx1) ? w01 : 0.f;
    g.w10 = (vy1 && vx0) ? w10 : 0.f;
    g.w11 = (vy1 && vx1) ? w11 : 0.f;
    int cy0 = min(max(y0, 0), NH - 1), cy1 = min(max(y1, 0), NH - 1);
    int cx0 = min(max(x0, 0), NW - 1), cx1 = min(max(x1, 0), NW - 1);
    g.v00 = *(const float4*)(xb + (cy0 * NW + cx0) * NC + lane * 4);
    g.v01 = *(const float4*)(xb + (cy0 * NW + cx1) * NC + lane * 4);
    g.v10 = *(const float4*)(xb + (cy1 * NW + cx0) * NC + lane * 4);
    g.v11 = *(const float4*)(xb + (cy1 * NW + cx1) * NC + lane * 4);
    int rot = pxl >> 3;
    int col = (lane + rot) & 31;
    g.dst = nbuf + pxl * 132 + col * 4;
}

__device__ __forceinline__ void samp_store(GS& g) {
    float4 s;
    s.x = g.w00 * g.v00.x + g.w01 * g.v01.x + g.w10 * g.v10.x + g.w11 * g.v11.x;
    s.y = g.w00 * g.v00.y + g.w01 * g.v01.y + g.w10 * g.v10.y + g.w11 * g.v11.y;
    s.z = g.w00 * g.v00.z + g.w01 * g.v01.z + g.w10 * g.v10.z + g.w11 * g.v11.z;
    s.w = g.w00 * g.v00.w + g.w01 * g.v01.w + g.w10 * g.v10.w + g.w11 * g.v11.w;
    *(float4*)g.dst = s;
}

// ---------------------------------------------------------------------------
// Kernel 4: deformable conv, no sampling duplication, pipelined gather.
// grid (2*NH, NB): CTA = 32 px (half row) x 128 outs, 256 thr, 2 CTA/SM.
// Thread map: pg = t&7 (4 px each), og = (t>>3)&15 (8 outs each), cs = t>>7.
// Per 4-ch chunk: 4 A-LDS.128 (1 wf) + 8 W-LDS.128 (1 wf) + 64 FFMA2.
// Gather for tap k+1 split load/store, 4 chunks apart, under tap-k GEMM.
// ---------------------------------------------------------------------------
__global__ void __launch_bounds__(256, 2) k_main(const float* __restrict__ bias,
                                                 float* __restrict__ out) {
    float* Ab0 = dsm;              // [32][132]
    float* Ab1 = dsm + 4224;
    float* wsm = dsm + 8448;       // [16 og][1028]

    int h = blockIdx.x >> 1;
    int half = blockIdx.x & 1;
    int b = blockIdx.y;
    int t = threadIdx.x;
    int wid = t >> 5, lane = t & 31;
    int pg = t & 7;
    int og = (t >> 3) & 15;
    int cs = t >> 7;
    int rot = pg >> 1;

    int pw = half * 32 + wid * 4 + (lane & 3);
    float4 pr = *(const float4*)(g_off + ((b * NH + h) * NW + pw) * 4);
    const float* xb = g_xt + (size_t)b * (NH * NW * NC);

    unsigned long long acc[32];
#pragma unroll
    for (int i = 0; i < 32; i++) acc[i] = 0ull;

    GS G;
    // prologue: sample tap 0 (4 px/warp) into Ab0, immediate
#pragma unroll
    for (int j = 0; j < 4; j++) {
        samp_load(0, j, half, G, pr, wid, lane, h, xb, Ab0);
        samp_store(G);
    }

    for (int k = 0; k < 9; k++) {
        __syncthreads();           // prev GEMM done: W + next A buffer free

        // W tile: linear cp.async of full 16-row smem image (65.8 KB)
        {
            const float* wsrc = g_wt6 + (size_t)k * (16 * WROW);
            for (int i = t; i < (16 * WROW) / 4; i += 256)
                cpa16(smaddr(wsm + i * 4), wsrc + i * 4);
            cpa_commit();
        }

        float* nbuf = (k & 1) ? Ab0 : Ab1;          // tap k+1 buffer
        const float* cbuf = (k & 1) ? Ab1 : Ab0;    // tap k buffer
        bool dos = (k < 8);
        if (dos) samp_load(k + 1, 0, half, G, pr, wid, lane, h, xb, nbuf);

        cpa_wait0();
        __syncthreads();           // W + samples visible

        const float* arow = cbuf + pg * 4 * 132;
        const float* wrow = wsm + og * WROW;
#pragma unroll 1
        for (int j = 0; j < 16; j++) {
            if (dos && (j & 3) == 2) {
                samp_store(G);
                int i = j >> 2;
                if (i < 3) samp_load(k + 1, i + 1, half, G, pr, wid, lane, h, xb, nbuf);
            }
            int c4 = cs * 16 + j;
            int col = (c4 + rot) & 31;
            unsigned long long aA[4], aB[4];
#pragma unroll
            for (int i = 0; i < 4; i++) {
                ulonglong2 av = *(const ulonglong2*)(arow + i * 132 + col * 4);
                aA[i] = av.x;      // channels 4c4, 4c4+1
                aB[i] = av.y;      // channels 4c4+2, 4c4+3
            }
            const float* wp = wrow + c4 * 32;
            {   // ch pair (4c4, 4c4+1)
                ulonglong2 q0 = ((const ulonglong2*)wp)[0];
                ulonglong2 q1 = ((const ulonglong2*)wp)[1];
                ulonglong2 q2 = ((const ulonglong2*)wp)[2];
                ulonglong2 q3 = ((const ulonglong2*)wp)[3];
                unsigned long long wv[8] = {q0.x, q0.y, q1.x, q1.y,
                                            q2.x, q2.y, q3.x, q3.y};
#pragma unroll
                for (int i = 0; i < 4; i++)
#pragma unroll
                    for (int o = 0; o < 8; o++)
                        asm("fma.rn.f32x2 %0, %1, %2, %0;"
                            : "+l"(acc[i * 8 + o]) : "l"(wv[o]), "l"(aA[i]));
            }
            {   // ch pair (4c4+2, 4c4+3)
                const float* wq = wp + 16;
                ulonglong2 q0 = ((const ulonglong2*)wq)[0];
                ulonglong2 q1 = ((const ulonglong2*)wq)[1];
                ulonglong2 q2 = ((const ulonglong2*)wq)[2];
                ulonglong2 q3 = ((const ulonglong2*)wq)[3];
                unsigned long long wv[8] = {q0.x, q0.y, q1.x, q1.y,
                                            q2.x, q2.y, q3.x, q3.y};
#pragma unroll
                for (int i = 0; i < 4; i++)
#pragma unroll
                    for (int o = 0; o < 8; o++)
                        asm("fma.rn.f32x2 %0, %1, %2, %0;"
                            : "+l"(acc[i * 8 + o]) : "l"(wv[o]), "l"(aB[i]));
            }
        }
    }

    // ---- channel-split reduction + output ----
    float val[32];
#pragma unroll
    for (int e = 0; e < 32; e++) {
        float lo, hi;
        asm("mov.b64 {%0, %1}, %2;" : "=f"(lo), "=f"(hi) : "l"(acc[e]));
        val[e] = lo + hi;
    }
    __syncthreads();               // last GEMM reads done; A region reusable

    if (cs == 1) {                 // stage partials: stride 33 -> conflict-free
        int slot = t & 127;
#pragma unroll
        for (int e = 0; e < 32; e++) dsm[slot * 33 + e] = val[e];
    }
    __syncthreads();
    if (cs == 0) {
        int slot = t;
#pragma unroll
        for (int e = 0; e < 32; e++) val[e] += dsm[slot * 33 + e];
#pragma unroll
        for (int o = 0; o < 8; o++) {
            int oo = og * 8 + o;
            float bv = __ldg(bias + oo);
            float* op = out + (((size_t)b * NC + oo) * NH + h) * NW + half * 32 + pg * 4;
            *(float4*)op = make_float4(val[0 * 8 + o] + bv, val[1 * 8 + o] + bv,
                                       val[2 * 8 + o] + bv, val[3 * 8 + o] + bv);
        }
    }
}

// ---------------------------------------------------------------------------
extern "C" void kernel_launch(void* const* d_in, const int* in_sizes, int n_in,
                              void* d_out, int out_size) {
    const float* x     = (const float*)d_in[0];
    const float* w_off = (const float*)d_in[1];
    const float* b_off = (const float*)d_in[2];
    const float* w     = (const float*)d_in[3];
    const float* bias  = (const float*)d_in[4];
    float* out = (float*)d_out;

    k_transpose<<<dim3(NB * NH, NC / 32, NW / 32), dim3(32, 8)>>>(x);
    k_wt6<<<(9 * 16 * WROW + 255) / 256, 256>>>(w);

    int off_smem = (3 * NW * NC + 4 * 9 * NC) * (int)sizeof(float);   // 116 KB
    cudaFuncSetAttribute(k_off, cudaFuncAttributeMaxDynamicSharedMemorySize, off_smem);
    k_off<<<dim3(NH, NB), 256, off_smem>>>(w_off, b_off);

    cudaFuncSetAttribute(k_main, cudaFuncAttributeMaxDynamicSharedMemorySize, KMAIN_SMEM);
    k_main<<<dim3(2 * NH, NB), 256, KMAIN_SMEM>>>(bias, out);
}